// round 13
// baseline (speedup 1.0000x reference)
#include <cuda_runtime.h>

#define B_  1024
#define G_  2000
#define S_  32
#define H_  64
#define NGC 20              // gene-GEMM split-K chunks (K=100 each)
#define NCHUNK (NGC + 14)   // + 8 (z1) + 4 (z2) + 2 (z3)
#define NZBLK  224          // 14 z-chunks * 16 row tiles
#define GENEBLK 250         // gene producers (R4 layout)
#define GGBLK   (16 * NGC)  // 320 gene-GEMM consumers
#define FINBLK  128         // finish blocks (8 rows each)
#define CHUNK_TGT 13        // producer blocks covering one gene-GEMM chunk
#define ROWSTRIDE (G_ * S_)  // 64000 floats per x row

// Scratch (static device globals — allocation-free per harness rules)
__device__ float g_gene[B_ * G_];            // 8 MB
__device__ float g_part[NCHUNK * B_ * H_];   // 8.9 MB
__device__ int   g_cdone[NGC];               // per-chunk producer counters (13)
__device__ int   g_zdone = 0;                // z-GEMM writer counter (224)
__device__ int   g_gdone = 0;                // gene-GEMM writer counter (320)
__device__ int   g_fin   = 0;                // finish-block counter (128)

// ---------------- packed fp32x2 helpers (sm_103a full-rate FMA path) ----------
__device__ __forceinline__ unsigned long long dup2(float v) {
    unsigned long long r;
    asm("mov.b64 %0, {%1, %1};" : "=l"(r) : "f"(v));
    return r;
}
__device__ __forceinline__ void ffma2(unsigned long long& d,
                                      unsigned long long a, unsigned long long b) {
    asm("fma.rn.f32x2 %0, %1, %2, %0;" : "+l"(d) : "l"(a), "l"(b));
}
__device__ __forceinline__ float2 unpk(unsigned long long v) {
    float2 r;
    asm("mov.b64 {%0, %1}, %2;" : "=f"(r.x), "=f"(r.y) : "l"(v));
    return r;
}
__device__ __forceinline__ int ld_acq(const int* p) {
    int v;
    asm volatile("ld.acquire.gpu.b32 %0, [%1];" : "=r"(v) : "l"(p) : "memory");
    return v;
}

// =============================================================================
// GEMM body (smem passed in): one 64x64 output tile over a <=512-wide K chunk;
// deterministic partial into g_part[c].
// =============================================================================
template <bool STREAM_A>
__device__ __forceinline__ void gemm_body(float* __restrict__ As,   // 32*66 floats
                                          float* __restrict__ Bs,   // 32*64 floats
                                          const float* __restrict__ A,
                                          const float* __restrict__ W,
                                          int lda, int k0, int klen,
                                          int c, int row0)
{
    const float* Ab = A + (size_t)row0 * lda + k0;
    const float* Wb = W + (size_t)k0 * 64;

    const int t    = threadIdx.x;
    const int tx   = t & 15;
    const int ty   = t >> 4;
    const int arow = t >> 3;
    const int af4  = (t & 7) * 4;
    const int ksteps = (klen + 31) >> 5;

    unsigned long long acc[2][4];
    #pragma unroll
    for (int p = 0; p < 2; p++)
        #pragma unroll
        for (int q = 0; q < 4; q++) acc[p][q] = 0ull;

    for (int ks = 0; ks < ksteps; ks++) {
        const int kk = ks * 32;
        const int kg = kk + af4;

        float4 av[2];
        #pragma unroll
        for (int i = 0; i < 2; i++) {
            const float* ap = Ab + (size_t)(arow + 32 * i) * lda;
            float4 v;
            if (kg + 3 < klen) {
                v = STREAM_A ? __ldcs((const float4*)(ap + kg))
                             : *(const float4*)(ap + kg);
            } else {
                v.x = (kg + 0 < klen) ? ap[kg + 0] : 0.0f;
                v.y = (kg + 1 < klen) ? ap[kg + 1] : 0.0f;
                v.z = (kg + 2 < klen) ? ap[kg + 2] : 0.0f;
                v.w = (kg + 3 < klen) ? ap[kg + 3] : 0.0f;
            }
            av[i] = v;
        }
        float4 bv2[2];
        #pragma unroll
        for (int i = 0; i < 2; i++) {
            const int q  = t + 256 * i;
            const int kr = kk + (q >> 4);
            float4 v = make_float4(0.f, 0.f, 0.f, 0.f);
            if (kr < klen) v = *(const float4*)(Wb + (size_t)kr * 64 + (q & 15) * 4);
            bv2[i] = v;
        }

        __syncthreads();
        #pragma unroll
        for (int i = 0; i < 2; i++) {
            As[(af4 + 0) * 66 + arow + 32 * i] = av[i].x;
            As[(af4 + 1) * 66 + arow + 32 * i] = av[i].y;
            As[(af4 + 2) * 66 + arow + 32 * i] = av[i].z;
            As[(af4 + 3) * 66 + arow + 32 * i] = av[i].w;
        }
        *(float4*)(Bs + (size_t)t * 4)         = bv2[0];
        *(float4*)(Bs + (size_t)(t + 256) * 4) = bv2[1];
        __syncthreads();

        #pragma unroll
        for (int k = 0; k < 32; k++) {
            const unsigned long long A0 = *(const unsigned long long*)&As[k * 66 + ty * 4];
            const unsigned long long A1 = *(const unsigned long long*)&As[k * 66 + ty * 4 + 2];
            const float4 bv = *(const float4*)(Bs + k * 64 + tx * 4);
            const unsigned long long Bq0 = dup2(bv.x);
            const unsigned long long Bq1 = dup2(bv.y);
            const unsigned long long Bq2 = dup2(bv.z);
            const unsigned long long Bq3 = dup2(bv.w);
            ffma2(acc[0][0], A0, Bq0); ffma2(acc[1][0], A1, Bq0);
            ffma2(acc[0][1], A0, Bq1); ffma2(acc[1][1], A1, Bq1);
            ffma2(acc[0][2], A0, Bq2); ffma2(acc[1][2], A1, Bq2);
            ffma2(acc[0][3], A0, Bq3); ffma2(acc[1][3], A1, Bq3);
        }
    }

    float* outp = g_part + ((size_t)c * B_ + row0 + ty * 4) * 64 + tx * 4;
    #pragma unroll
    for (int p = 0; p < 2; p++) {
        const float2 u0 = unpk(acc[p][0]);
        const float2 u1 = unpk(acc[p][1]);
        const float2 u2 = unpk(acc[p][2]);
        const float2 u3 = unpk(acc[p][3]);
        *(float4*)(outp + (size_t)(2 * p) * 64)     = make_float4(u0.x, u1.x, u2.x, u3.x);
        *(float4*)(outp + (size_t)(2 * p + 1) * 64) = make_float4(u0.y, u1.y, u2.y, u3.y);
    }
}

// =============================================================================
// Mega kernel — four block populations, ONE launch (R11 structure + two-phase
// finish gating):
//  [0, 224):    z-GEMM chunks                      -> fence + g_zdone++
//  [224, 474):  gene producers (block completes p-groups {2gb, 2gb+1})
//               -> fence + g_cdone[chunk(s)]++   (coarse per-chunk gating;
//               NO concurrent consumer traffic during the producer phase)
//  [474, 794):  gene-GEMM consumers: spin g_cdone[c]==13, gemm
//               -> fence + g_gdone++
//  [794, 922):  finish (8 rows/block): pre-stage fW1/fW2; gate 1 (g_zdone==224)
//               -> reduce z partials EARLY (hidden under producers);
//               gate 2 (g_gdone==320) -> a0 + MLP. Last block resets counters.
// =============================================================================
__global__ void __launch_bounds__(256, 5) mega_kernel(
    const float* __restrict__ x,
    const float* __restrict__ z1, const float* __restrict__ z2,
    const float* __restrict__ z3,
    const float* __restrict__ Wg, const float* __restrict__ bg,
    const float* __restrict__ W0, const float* __restrict__ b0,
    const float* __restrict__ W1, const float* __restrict__ b1,
    const float* __restrict__ W2, const float* __restrict__ b2,
    const float* __restrict__ W3, const float* __restrict__ b3,
    const float* __restrict__ w1, const float* __restrict__ w2,
    const float* __restrict__ w3,
    const float* __restrict__ fW1, const float* __restrict__ fb1,
    const float* __restrict__ fW2, const float* __restrict__ fb2,
    const float* __restrict__ fW3, const float* __restrict__ fb3,
    float* __restrict__ out)
{
    __shared__ __align__(128) float pool[8720];   // max(GEMM 4160, finish 8720)

    const int bid = blockIdx.x;
    const int t   = threadIdx.x;

    if (bid < NZBLK) {
        const int zc   = bid >> 4;            // 0..13
        const int row0 = (bid & 15) * 64;
        const float* A; const float* W; int lda, k0;
        if (zc < 8)       { A = z1; W = W1; lda = 4096; k0 = zc * 512; }
        else if (zc < 12) { A = z2; W = W2; lda = 2048; k0 = (zc - 8)  * 512; }
        else              { A = z3; W = W3; lda = 1024; k0 = (zc - 12) * 512; }
        gemm_body<true>(pool, pool + 2112, A, W, lda, k0, 512, NGC + zc, row0);
        __syncthreads();
        __threadfence();
        if (t == 0) atomicAdd(&g_zdone, 1);
        return;
    }

    if (bid < NZBLK + GENEBLK) {
        // ---- gene producers: 2000 warp-tasks = 500 p-groups x 4 b-chunks ----
        const int gb   = bid - NZBLK;            // 0..249
        const int lane = t & 31;
        const int w    = gb * 8 + (t >> 5);      // 0..1999
        const int p    = w >> 2;                 // gene group 0..499
        const int b0r  = (w & 3) * 256;          // b-chunk of 256 rows

        const float4 wv  = *(const float4*)(Wg + (size_t)p * 128 + lane * 4);
        const int    g   = p * 4 + (lane >> 3);
        const float  bias = __ldg(bg + g);
        const bool   is_store_lane = (lane & 7) == 0;

        const float* xp = x + (size_t)b0r * ROWSTRIDE + (size_t)p * 128 + lane * 4;
        float* gp = g_gene + (size_t)b0r * G_ + g;

        for (int i = 0; i < 256; i += 8) {
            float4 xv[8];
            #pragma unroll
            for (int j = 0; j < 8; j++)
                xv[j] = __ldcs((const float4*)(xp + (size_t)(i + j) * ROWSTRIDE));

            float d[8];
            #pragma unroll
            for (int j = 0; j < 8; j++)
                d[j] = xv[j].x * wv.x + xv[j].y * wv.y + xv[j].z * wv.z + xv[j].w * wv.w;

            #pragma unroll
            for (int j = 0; j < 8; j++) {
                d[j] += __shfl_down_sync(0xffffffffu, d[j], 4);
                d[j] += __shfl_down_sync(0xffffffffu, d[j], 2);
                d[j] += __shfl_down_sync(0xffffffffu, d[j], 1);
            }
            if (is_store_lane) {
                #pragma unroll
                for (int j = 0; j < 8; j++)
                    gp[(size_t)(i + j) * G_] = fmaxf(d[j] + bias, 0.0f);
            }
        }

        __syncthreads();
        __threadfence();
        if (t == 0) {
            // block gb fully produced p-groups 2gb and 2gb+1
            const int ca  = (2 * gb) / 25;       // 25 p-groups per chunk
            const int cb2 = (2 * gb + 1) / 25;
            atomicAdd(&g_cdone[ca], 1);
            if (cb2 != ca) atomicAdd(&g_cdone[cb2], 1);
        }
        return;
    }

    if (bid < NZBLK + GENEBLK + GGBLK) {
        // ---- gene-GEMM consumers: per-chunk gate ----
        const int cb   = bid - (NZBLK + GENEBLK);   // 0..319
        const int c    = cb >> 4;                   // 0..NGC-1
        const int row0 = (cb & 15) * 64;
        if (t == 0) {
            while (ld_acq(&g_cdone[c]) < CHUNK_TGT) __nanosleep(128);
        }
        __syncthreads();

        gemm_body<false>(pool, pool + 2112, g_gene, W0, G_, c * 100, 100, c, row0);
        __syncthreads();
        __threadfence();
        if (t == 0) atomicAdd(&g_gdone, 1);
        return;
    }

    // ---- finish population: 128 blocks x 8 rows, two-phase gating ----
    float* sW1 = pool;                                   // 4096
    float* sW2 = pool + 4096;                            // 4096
    float (*sbuf)[64] = (float(*)[64])(pool + 8192);     // 8*64
    float* sred = pool + 8192 + 512;                     // 16

    const int h   = t & 63;
    const int r   = t >> 6;       // slot 0..3; thread handles rows r and r+4
    const int wid = t >> 5;

    // PRE-STAGE weights while producers still run
    #pragma unroll
    for (int i = 0; i < 4; i++) {
        ((float4*)sW1)[t + 256 * i] = ((const float4*)fW1)[t + 256 * i];
        ((float4*)sW2)[t + 256 * i] = ((const float4*)fW2)[t + 256 * i];
    }

    const int fb  = bid - (NZBLK + GENEBLK + GGBLK);
    const int b0r = fb * 8;

    // ---- gate 1: z partials ready (early, ~t=18us) -> weighted z-fusion ----
    if (t == 0) {
        while (ld_acq(&g_zdone) < NZBLK) __nanosleep(128);
    }
    __syncthreads();

    float s[2];
    #pragma unroll
    for (int rr = 0; rr < 2; rr++) {
        const int b = b0r + r + rr * 4;
        float a1 = 0.f, a2 = 0.f, a3 = 0.f;
        #pragma unroll
        for (int cc = NGC;     cc < NGC + 8;  cc++) a1 += g_part[((size_t)cc * B_ + b) * 64 + h];
        #pragma unroll
        for (int cc = NGC + 8; cc < NGC + 12; cc++) a2 += g_part[((size_t)cc * B_ + b) * 64 + h];
        #pragma unroll
        for (int cc = NGC + 12; cc < NGC + 14; cc++) a3 += g_part[((size_t)cc * B_ + b) * 64 + h];
        s[rr] = fmaxf(a1 + b1[h], 0.f) * w1[h]
              + fmaxf(a2 + b2[h], 0.f) * w2[h]
              + fmaxf(a3 + b3[h], 0.f) * w3[h];
    }

    // ---- gate 2: gene partials ready -> a0 + MLP ----
    if (t == 0) {
        while (ld_acq(&g_gdone) < GGBLK) __nanosleep(128);
    }
    __syncthreads();

    float dd[2];
    #pragma unroll
    for (int rr = 0; rr < 2; rr++) {
        const int b = b0r + r + rr * 4;
        float a0 = 0.f;
        #pragma unroll
        for (int cc = 0; cc < NGC; cc++) a0 += g_part[((size_t)cc * B_ + b) * 64 + h];
        dd[rr] = fmaxf(a0 + b0[h], 0.f) + s[rr];
    }

    sbuf[r][h]     = dd[0];
    sbuf[r + 4][h] = dd[1];
    __syncthreads();
    float acc0 = fb1[h], acc1 = fb1[h];
    #pragma unroll
    for (int k = 0; k < 64; k++) {
        acc0 = fmaf(sbuf[r][k],     sW1[k * 64 + h], acc0);
        acc1 = fmaf(sbuf[r + 4][k], sW1[k * 64 + h], acc1);
    }
    const float hv0 = fmaxf(acc0, 0.f);
    const float hv1 = fmaxf(acc1, 0.f);
    __syncthreads();
    sbuf[r][h]     = hv0;
    sbuf[r + 4][h] = hv1;
    __syncthreads();
    acc0 = fb2[h]; acc1 = fb2[h];
    #pragma unroll
    for (int k = 0; k < 64; k++) {
        acc0 = fmaf(sbuf[r][k],     sW2[k * 64 + h], acc0);
        acc1 = fmaf(sbuf[r + 4][k], sW2[k * 64 + h], acc1);
    }
    const float h20 = fmaxf(acc0, 0.f);
    const float h21 = fmaxf(acc1, 0.f);

    float v0 = h20 * fW3[h];
    float v1 = h21 * fW3[h];
    #pragma unroll
    for (int off = 16; off; off >>= 1) {
        v0 += __shfl_down_sync(0xffffffffu, v0, off);
        v1 += __shfl_down_sync(0xffffffffu, v1, off);
    }
    if ((t & 31) == 0) { sred[wid] = v0; sred[8 + wid] = v1; }
    __syncthreads();
    if (h == 0) {
        out[b0r + r]     = sred[2 * r] + sred[2 * r + 1] + fb3[0];
        out[b0r + r + 4] = sred[8 + 2 * r] + sred[8 + 2 * r + 1] + fb3[0];
    }

    // Counter reset by the LAST finish block (all gates passed by then).
    __syncthreads();
    if (t == 0) {
        const int o = atomicAdd(&g_fin, 1);
        if (o == FINBLK - 1) {
            #pragma unroll
            for (int c = 0; c < NGC; c++) g_cdone[c] = 0;
            g_zdone = 0;
            g_gdone = 0;
            g_fin   = 0;
            __threadfence();
        }
    }
}

// =============================================================================
// Launcher (graph-capturable: ONE kernel launch, no sync, no alloc)
// =============================================================================
extern "C" void kernel_launch(void* const* d_in, const int* in_sizes, int n_in,
                              void* d_out, int out_size)
{
    const float* x   = (const float*)d_in[0];
    const float* z1  = (const float*)d_in[1];
    const float* z2  = (const float*)d_in[2];
    const float* z3  = (const float*)d_in[3];
    const float* Wg  = (const float*)d_in[4];
    const float* bg  = (const float*)d_in[5];
    const float* W0  = (const float*)d_in[6];
    const float* b0  = (const float*)d_in[7];
    const float* W1  = (const float*)d_in[8];
    const float* b1  = (const float*)d_in[9];
    const float* W2  = (const float*)d_in[10];
    const float* b2  = (const float*)d_in[11];
    const float* W3  = (const float*)d_in[12];
    const float* b3  = (const float*)d_in[13];
    const float* w1  = (const float*)d_in[14];
    const float* w2  = (const float*)d_in[15];
    const float* w3  = (const float*)d_in[16];
    const float* fW1 = (const float*)d_in[17];
    const float* fb1 = (const float*)d_in[18];
    const float* fW2 = (const float*)d_in[19];
    const float* fb2 = (const float*)d_in[20];
    const float* fW3 = (const float*)d_in[21];
    const float* fb3 = (const float*)d_in[22];
    float* out = (float*)d_out;

    mega_kernel<<<NZBLK + GENEBLK + GGBLK + FINBLK, 256>>>(
        x, z1, z2, z3, Wg, bg, W0, b0, W1, b1, W2, b2, W3, b3,
        w1, w2, w3, fW1, fb1, fW2, fb2, fW3, fb3, out);
}

// round 14
// speedup vs baseline: 1.3758x; 1.3758x over previous
#include <cuda_runtime.h>

#define B_  1024
#define G_  2000
#define S_  32
#define H_  64
#define NGC 20              // gene-GEMM split-K chunks (K=100 each)
#define NCHUNK (NGC + 14)   // + 8 (z1) + 4 (z2) + 2 (z3)
#define NZBLK  224          // 14 z-chunks * 16 row tiles
#define GENEBLK 250         // gene producers (R4 layout)
#define GGBLK   (16 * NGC)  // 320 gene-GEMM consumers
#define FINBLK  128         // finish blocks (8 rows each)
#define CHUNK_TGT 13        // producer blocks covering one gene-GEMM chunk
#define PDONE_TARGET (NZBLK + GGBLK)   // 544 g_part writers
#define ROWSTRIDE (G_ * S_)  // 64000 floats per x row

// Scratch (static device globals — allocation-free per harness rules)
__device__ float g_gene[B_ * G_];            // 8 MB
__device__ float g_part[NCHUNK * B_ * H_];   // 8.9 MB
__device__ int   g_cdone[NGC];               // per-chunk producer counters (13)
__device__ int   g_pdone = 0;                // g_part-writer counter (544)
__device__ int   g_fin   = 0;                // finish-block counter (128)

// ---------------- packed fp32x2 helpers (sm_103a full-rate FMA path) ----------
__device__ __forceinline__ unsigned long long dup2(float v) {
    unsigned long long r;
    asm("mov.b64 %0, {%1, %1};" : "=l"(r) : "f"(v));
    return r;
}
__device__ __forceinline__ void ffma2(unsigned long long& d,
                                      unsigned long long a, unsigned long long b) {
    asm("fma.rn.f32x2 %0, %1, %2, %0;" : "+l"(d) : "l"(a), "l"(b));
}
__device__ __forceinline__ float2 unpk(unsigned long long v) {
    float2 r;
    asm("mov.b64 {%0, %1}, %2;" : "=f"(r.x), "=f"(r.y) : "l"(v));
    return r;
}
__device__ __forceinline__ int ld_acq(const int* p) {
    int v;
    asm volatile("ld.acquire.gpu.b32 %0, [%1];" : "=r"(v) : "l"(p) : "memory");
    return v;
}
__device__ __forceinline__ void prefetch_l2(const void* p) {
    asm volatile("prefetch.global.L2 [%0];" :: "l"(p));
}

// =============================================================================
// GEMM body (smem passed in): one 64x64 output tile over a <=512-wide K chunk;
// deterministic partial into g_part[c].
// =============================================================================
template <bool STREAM_A>
__device__ __forceinline__ void gemm_body(float* __restrict__ As,   // 32*66 floats
                                          float* __restrict__ Bs,   // 32*64 floats
                                          const float* __restrict__ A,
                                          const float* __restrict__ W,
                                          int lda, int k0, int klen,
                                          int c, int row0)
{
    const float* Ab = A + (size_t)row0 * lda + k0;
    const float* Wb = W + (size_t)k0 * 64;

    const int t    = threadIdx.x;
    const int tx   = t & 15;
    const int ty   = t >> 4;
    const int arow = t >> 3;
    const int af4  = (t & 7) * 4;
    const int ksteps = (klen + 31) >> 5;

    unsigned long long acc[2][4];
    #pragma unroll
    for (int p = 0; p < 2; p++)
        #pragma unroll
        for (int q = 0; q < 4; q++) acc[p][q] = 0ull;

    for (int ks = 0; ks < ksteps; ks++) {
        const int kk = ks * 32;
        const int kg = kk + af4;

        float4 av[2];
        #pragma unroll
        for (int i = 0; i < 2; i++) {
            const float* ap = Ab + (size_t)(arow + 32 * i) * lda;
            float4 v;
            if (kg + 3 < klen) {
                v = STREAM_A ? __ldcs((const float4*)(ap + kg))
                             : *(const float4*)(ap + kg);
            } else {
                v.x = (kg + 0 < klen) ? ap[kg + 0] : 0.0f;
                v.y = (kg + 1 < klen) ? ap[kg + 1] : 0.0f;
                v.z = (kg + 2 < klen) ? ap[kg + 2] : 0.0f;
                v.w = (kg + 3 < klen) ? ap[kg + 3] : 0.0f;
            }
            av[i] = v;
        }
        float4 bv2[2];
        #pragma unroll
        for (int i = 0; i < 2; i++) {
            const int q  = t + 256 * i;
            const int kr = kk + (q >> 4);
            float4 v = make_float4(0.f, 0.f, 0.f, 0.f);
            if (kr < klen) v = *(const float4*)(Wb + (size_t)kr * 64 + (q & 15) * 4);
            bv2[i] = v;
        }

        __syncthreads();
        #pragma unroll
        for (int i = 0; i < 2; i++) {
            As[(af4 + 0) * 66 + arow + 32 * i] = av[i].x;
            As[(af4 + 1) * 66 + arow + 32 * i] = av[i].y;
            As[(af4 + 2) * 66 + arow + 32 * i] = av[i].z;
            As[(af4 + 3) * 66 + arow + 32 * i] = av[i].w;
        }
        *(float4*)(Bs + (size_t)t * 4)         = bv2[0];
        *(float4*)(Bs + (size_t)(t + 256) * 4) = bv2[1];
        __syncthreads();

        #pragma unroll
        for (int k = 0; k < 32; k++) {
            const unsigned long long A0 = *(const unsigned long long*)&As[k * 66 + ty * 4];
            const unsigned long long A1 = *(const unsigned long long*)&As[k * 66 + ty * 4 + 2];
            const float4 bv = *(const float4*)(Bs + k * 64 + tx * 4);
            const unsigned long long Bq0 = dup2(bv.x);
            const unsigned long long Bq1 = dup2(bv.y);
            const unsigned long long Bq2 = dup2(bv.z);
            const unsigned long long Bq3 = dup2(bv.w);
            ffma2(acc[0][0], A0, Bq0); ffma2(acc[1][0], A1, Bq0);
            ffma2(acc[0][1], A0, Bq1); ffma2(acc[1][1], A1, Bq1);
            ffma2(acc[0][2], A0, Bq2); ffma2(acc[1][2], A1, Bq2);
            ffma2(acc[0][3], A0, Bq3); ffma2(acc[1][3], A1, Bq3);
        }
    }

    float* outp = g_part + ((size_t)c * B_ + row0 + ty * 4) * 64 + tx * 4;
    #pragma unroll
    for (int p = 0; p < 2; p++) {
        const float2 u0 = unpk(acc[p][0]);
        const float2 u1 = unpk(acc[p][1]);
        const float2 u2 = unpk(acc[p][2]);
        const float2 u3 = unpk(acc[p][3]);
        *(float4*)(outp + (size_t)(2 * p) * 64)     = make_float4(u0.x, u1.x, u2.x, u3.x);
        *(float4*)(outp + (size_t)(2 * p + 1) * 64) = make_float4(u0.y, u1.y, u2.y, u3.y);
    }
}

// =============================================================================
// Mega kernel — four block populations, ONE launch (exact R11 structure; the
// only addition is a one-shot W0 L2-prefetch by consumers at block START,
// during the warm-up window, NOT mid-producer-phase):
//  [0, 224):    z-GEMM chunks                      -> fence + g_pdone++
//  [224, 474):  gene producers (block completes p-groups {2gb, 2gb+1})
//               -> fence + g_cdone[chunk(s)]++
//  [474, 794):  gene-GEMM consumers: prefetch W0 chunk to L2, spin
//               g_cdone[c]==13, gemm -> fence + g_pdone++
//  [794, 922):  finish (8 rows/block): pre-stage fW1/fW2, spin g_pdone==544,
//               reduce partials + fusion + MLP -> out. Last block resets ctrs.
// =============================================================================
__global__ void __launch_bounds__(256, 5) mega_kernel(
    const float* __restrict__ x,
    const float* __restrict__ z1, const float* __restrict__ z2,
    const float* __restrict__ z3,
    const float* __restrict__ Wg, const float* __restrict__ bg,
    const float* __restrict__ W0, const float* __restrict__ b0,
    const float* __restrict__ W1, const float* __restrict__ b1,
    const float* __restrict__ W2, const float* __restrict__ b2,
    const float* __restrict__ W3, const float* __restrict__ b3,
    const float* __restrict__ w1, const float* __restrict__ w2,
    const float* __restrict__ w3,
    const float* __restrict__ fW1, const float* __restrict__ fb1,
    const float* __restrict__ fW2, const float* __restrict__ fb2,
    const float* __restrict__ fW3, const float* __restrict__ fb3,
    float* __restrict__ out)
{
    __shared__ __align__(128) float pool[8720];   // max(GEMM 4160, finish 8720)

    const int bid = blockIdx.x;
    const int t   = threadIdx.x;

    if (bid < NZBLK) {
        const int zc   = bid >> 4;            // 0..13
        const int row0 = (bid & 15) * 64;
        const float* A; const float* W; int lda, k0;
        if (zc < 8)       { A = z1; W = W1; lda = 4096; k0 = zc * 512; }
        else if (zc < 12) { A = z2; W = W2; lda = 2048; k0 = (zc - 8)  * 512; }
        else              { A = z3; W = W3; lda = 1024; k0 = (zc - 12) * 512; }
        gemm_body<true>(pool, pool + 2112, A, W, lda, k0, 512, NGC + zc, row0);
        __syncthreads();
        __threadfence();
        if (t == 0) atomicAdd(&g_pdone, 1);
        return;
    }

    if (bid < NZBLK + GENEBLK) {
        // ---- gene producers: 2000 warp-tasks = 500 p-groups x 4 b-chunks ----
        const int gb   = bid - NZBLK;            // 0..249
        const int lane = t & 31;
        const int w    = gb * 8 + (t >> 5);      // 0..1999
        const int p    = w >> 2;                 // gene group 0..499
        const int b0r  = (w & 3) * 256;          // b-chunk of 256 rows

        const float4 wv  = *(const float4*)(Wg + (size_t)p * 128 + lane * 4);
        const int    g   = p * 4 + (lane >> 3);
        const float  bias = __ldg(bg + g);
        const bool   is_store_lane = (lane & 7) == 0;

        const float* xp = x + (size_t)b0r * ROWSTRIDE + (size_t)p * 128 + lane * 4;
        float* gp = g_gene + (size_t)b0r * G_ + g;

        for (int i = 0; i < 256; i += 8) {
            float4 xv[8];
            #pragma unroll
            for (int j = 0; j < 8; j++)
                xv[j] = __ldcs((const float4*)(xp + (size_t)(i + j) * ROWSTRIDE));

            float d[8];
            #pragma unroll
            for (int j = 0; j < 8; j++)
                d[j] = xv[j].x * wv.x + xv[j].y * wv.y + xv[j].z * wv.z + xv[j].w * wv.w;

            #pragma unroll
            for (int j = 0; j < 8; j++) {
                d[j] += __shfl_down_sync(0xffffffffu, d[j], 4);
                d[j] += __shfl_down_sync(0xffffffffu, d[j], 2);
                d[j] += __shfl_down_sync(0xffffffffu, d[j], 1);
            }
            if (is_store_lane) {
                #pragma unroll
                for (int j = 0; j < 8; j++)
                    gp[(size_t)(i + j) * G_] = fmaxf(d[j] + bias, 0.0f);
            }
        }

        __syncthreads();
        __threadfence();
        if (t == 0) {
            // block gb fully produced p-groups 2gb and 2gb+1
            const int ca  = (2 * gb) / 25;       // 25 p-groups per chunk
            const int cb2 = (2 * gb + 1) / 25;
            atomicAdd(&g_cdone[ca], 1);
            if (cb2 != ca) atomicAdd(&g_cdone[cb2], 1);
        }
        return;
    }

    if (bid < NZBLK + GENEBLK + GGBLK) {
        // ---- gene-GEMM consumers: per-chunk gate ----
        const int cb   = bid - (NZBLK + GENEBLK);   // 0..319
        const int c    = cb >> 4;                   // 0..NGC-1
        const int row0 = (cb & 15) * 64;

        // One-shot L2 prefetch of this chunk's W0 rows (100 x 64 floats =
        // 25.6 KB) at block start — warm-up window, before producers saturate.
        {
            const float* wbase = W0 + (size_t)(c * 100) * 64;
            for (int off = t * 32; off < 100 * 64; off += 256 * 32)
                prefetch_l2(wbase + off);
        }

        if (t == 0) {
            while (ld_acq(&g_cdone[c]) < CHUNK_TGT) __nanosleep(128);
        }
        __syncthreads();

        gemm_body<false>(pool, pool + 2112, g_gene, W0, G_, c * 100, 100, c, row0);
        __syncthreads();
        __threadfence();
        if (t == 0) atomicAdd(&g_pdone, 1);
        return;
    }

    // ---- finish population: 128 blocks x 8 rows (R11 single-gate form) ----
    float* sW1 = pool;                                   // 4096
    float* sW2 = pool + 4096;                            // 4096
    float (*sbuf)[64] = (float(*)[64])(pool + 8192);     // 8*64
    float* sred = pool + 8192 + 512;                     // 16

    const int h   = t & 63;
    const int r   = t >> 6;       // slot 0..3; thread handles rows r and r+4
    const int wid = t >> 5;

    // PRE-STAGE weights while producers still run
    #pragma unroll
    for (int i = 0; i < 4; i++) {
        ((float4*)sW1)[t + 256 * i] = ((const float4*)fW1)[t + 256 * i];
        ((float4*)sW2)[t + 256 * i] = ((const float4*)fW2)[t + 256 * i];
    }

    if (t == 0) {
        while (ld_acq(&g_pdone) < PDONE_TARGET) __nanosleep(128);
    }
    __syncthreads();   // gate + weight-staging visibility

    const int fb  = bid - (NZBLK + GENEBLK + GGBLK);
    const int b0r = fb * 8;

    float dd[2];
    #pragma unroll
    for (int rr = 0; rr < 2; rr++) {
        const int b = b0r + r + rr * 4;
        float a0 = 0.f, a1 = 0.f, a2 = 0.f, a3 = 0.f;
        #pragma unroll
        for (int cc = 0;       cc < NGC;      cc++) a0 += g_part[((size_t)cc * B_ + b) * 64 + h];
        #pragma unroll
        for (int cc = NGC;     cc < NGC + 8;  cc++) a1 += g_part[((size_t)cc * B_ + b) * 64 + h];
        #pragma unroll
        for (int cc = NGC + 8; cc < NGC + 12; cc++) a2 += g_part[((size_t)cc * B_ + b) * 64 + h];
        #pragma unroll
        for (int cc = NGC + 12; cc < NGC + 14; cc++) a3 += g_part[((size_t)cc * B_ + b) * 64 + h];

        float d = fmaxf(a0 + b0[h], 0.f);
        d += fmaxf(a1 + b1[h], 0.f) * w1[h];
        d += fmaxf(a2 + b2[h], 0.f) * w2[h];
        d += fmaxf(a3 + b3[h], 0.f) * w3[h];
        dd[rr] = d;
    }

    sbuf[r][h]     = dd[0];
    sbuf[r + 4][h] = dd[1];
    __syncthreads();
    float acc0 = fb1[h], acc1 = fb1[h];
    #pragma unroll
    for (int k = 0; k < 64; k++) {
        acc0 = fmaf(sbuf[r][k],     sW1[k * 64 + h], acc0);
        acc1 = fmaf(sbuf[r + 4][k], sW1[k * 64 + h], acc1);
    }
    const float hv0 = fmaxf(acc0, 0.f);
    const float hv1 = fmaxf(acc1, 0.f);
    __syncthreads();
    sbuf[r][h]     = hv0;
    sbuf[r + 4][h] = hv1;
    __syncthreads();
    acc0 = fb2[h]; acc1 = fb2[h];
    #pragma unroll
    for (int k = 0; k < 64; k++) {
        acc0 = fmaf(sbuf[r][k],     sW2[k * 64 + h], acc0);
        acc1 = fmaf(sbuf[r + 4][k], sW2[k * 64 + h], acc1);
    }
    const float h20 = fmaxf(acc0, 0.f);
    const float h21 = fmaxf(acc1, 0.f);

    float v0 = h20 * fW3[h];
    float v1 = h21 * fW3[h];
    #pragma unroll
    for (int off = 16; off; off >>= 1) {
        v0 += __shfl_down_sync(0xffffffffu, v0, off);
        v1 += __shfl_down_sync(0xffffffffu, v1, off);
    }
    if ((t & 31) == 0) { sred[wid] = v0; sred[8 + wid] = v1; }
    __syncthreads();
    if (h == 0) {
        out[b0r + r]     = sred[2 * r] + sred[2 * r + 1] + fb3[0];
        out[b0r + r + 4] = sred[8 + 2 * r] + sred[8 + 2 * r + 1] + fb3[0];
    }

    // Counter reset by the LAST finish block (all gates passed by then).
    __syncthreads();
    if (t == 0) {
        const int o = atomicAdd(&g_fin, 1);
        if (o == FINBLK - 1) {
            #pragma unroll
            for (int c = 0; c < NGC; c++) g_cdone[c] = 0;
            g_pdone = 0;
            g_fin   = 0;
            __threadfence();
        }
    }
}

// =============================================================================
// Launcher (graph-capturable: ONE kernel launch, no sync, no alloc)
// =============================================================================
extern "C" void kernel_launch(void* const* d_in, const int* in_sizes, int n_in,
                              void* d_out, int out_size)
{
    const float* x   = (const float*)d_in[0];
    const float* z1  = (const float*)d_in[1];
    const float* z2  = (const float*)d_in[2];
    const float* z3  = (const float*)d_in[3];
    const float* Wg  = (const float*)d_in[4];
    const float* bg  = (const float*)d_in[5];
    const float* W0  = (const float*)d_in[6];
    const float* b0  = (const float*)d_in[7];
    const float* W1  = (const float*)d_in[8];
    const float* b1  = (const float*)d_in[9];
    const float* W2  = (const float*)d_in[10];
    const float* b2  = (const float*)d_in[11];
    const float* W3  = (const float*)d_in[12];
    const float* b3  = (const float*)d_in[13];
    const float* w1  = (const float*)d_in[14];
    const float* w2  = (const float*)d_in[15];
    const float* w3  = (const float*)d_in[16];
    const float* fW1 = (const float*)d_in[17];
    const float* fb1 = (const float*)d_in[18];
    const float* fW2 = (const float*)d_in[19];
    const float* fb2 = (const float*)d_in[20];
    const float* fW3 = (const float*)d_in[21];
    const float* fb3 = (const float*)d_in[22];
    float* out = (float*)d_out;

    mega_kernel<<<NZBLK + GENEBLK + GGBLK + FINBLK, 256>>>(
        x, z1, z2, z3, Wg, bg, W0, b0, W1, b1, W2, b2, W3, b3,
        w1, w2, w3, fW1, fb1, fW2, fb2, fW3, fb3, out);
}

// round 15
// speedup vs baseline: 1.3840x; 1.0059x over previous
#include <cuda_runtime.h>

#define B_  1024
#define G_  2000
#define S_  32
#define H_  64
#define NGC 20              // gene-GEMM split-K chunks (K=100 each)
#define NCHUNK (NGC + 14)   // + 8 (z1) + 4 (z2) + 2 (z3)
#define NZBLK  224          // 14 z-chunks * 16 row tiles
#define GENEBLK 250         // gene producers (R4 layout)
#define GGBLK   (16 * NGC)  // 320 gene-GEMM consumers
#define FINBLK  128         // finish blocks (8 rows each)
#define CHUNK_TGT 13        // producer blocks covering one gene-GEMM chunk
#define PDONE_TARGET (NZBLK + GGBLK)   // 544 g_part writers
#define ROWSTRIDE (G_ * S_)  // 64000 floats per x row

// Scratch (static device globals — allocation-free per harness rules)
__device__ float g_gene[B_ * G_];            // 8 MB
__device__ float g_part[NCHUNK * B_ * H_];   // 8.9 MB
__device__ int   g_cdone[NGC];               // per-chunk producer counters (13)
__device__ int   g_pdone = 0;                // g_part-writer counter (544)
__device__ int   g_fin   = 0;                // finish-block counter (128)

// ---------------- packed fp32x2 helpers (sm_103a full-rate FMA path) ----------
__device__ __forceinline__ unsigned long long dup2(float v) {
    unsigned long long r;
    asm("mov.b64 %0, {%1, %1};" : "=l"(r) : "f"(v));
    return r;
}
__device__ __forceinline__ void ffma2(unsigned long long& d,
                                      unsigned long long a, unsigned long long b) {
    asm("fma.rn.f32x2 %0, %1, %2, %0;" : "+l"(d) : "l"(a), "l"(b));
}
__device__ __forceinline__ float2 unpk(unsigned long long v) {
    float2 r;
    asm("mov.b64 {%0, %1}, %2;" : "=f"(r.x), "=f"(r.y) : "l"(v));
    return r;
}
__device__ __forceinline__ int ld_acq(const int* p) {
    int v;
    asm volatile("ld.acquire.gpu.b32 %0, [%1];" : "=r"(v) : "l"(p) : "memory");
    return v;
}

// =============================================================================
// GEMM body (smem passed in): one 64x64 output tile over a <=512-wide K chunk;
// deterministic partial into g_part[c].
// =============================================================================
template <bool STREAM_A>
__device__ __forceinline__ void gemm_body(float* __restrict__ As,   // 32*66 floats
                                          float* __restrict__ Bs,   // 32*64 floats
                                          const float* __restrict__ A,
                                          const float* __restrict__ W,
                                          int lda, int k0, int klen,
                                          int c, int row0)
{
    const float* Ab = A + (size_t)row0 * lda + k0;
    const float* Wb = W + (size_t)k0 * 64;

    const int t    = threadIdx.x;
    const int tx   = t & 15;
    const int ty   = t >> 4;
    const int arow = t >> 3;
    const int af4  = (t & 7) * 4;
    const int ksteps = (klen + 31) >> 5;

    unsigned long long acc[2][4];
    #pragma unroll
    for (int p = 0; p < 2; p++)
        #pragma unroll
        for (int q = 0; q < 4; q++) acc[p][q] = 0ull;

    for (int ks = 0; ks < ksteps; ks++) {
        const int kk = ks * 32;
        const int kg = kk + af4;

        float4 av[2];
        #pragma unroll
        for (int i = 0; i < 2; i++) {
            const float* ap = Ab + (size_t)(arow + 32 * i) * lda;
            float4 v;
            if (kg + 3 < klen) {
                v = STREAM_A ? __ldcs((const float4*)(ap + kg))
                             : *(const float4*)(ap + kg);
            } else {
                v.x = (kg + 0 < klen) ? ap[kg + 0] : 0.0f;
                v.y = (kg + 1 < klen) ? ap[kg + 1] : 0.0f;
                v.z = (kg + 2 < klen) ? ap[kg + 2] : 0.0f;
                v.w = (kg + 3 < klen) ? ap[kg + 3] : 0.0f;
            }
            av[i] = v;
        }
        float4 bv2[2];
        #pragma unroll
        for (int i = 0; i < 2; i++) {
            const int q  = t + 256 * i;
            const int kr = kk + (q >> 4);
            float4 v = make_float4(0.f, 0.f, 0.f, 0.f);
            if (kr < klen) v = *(const float4*)(Wb + (size_t)kr * 64 + (q & 15) * 4);
            bv2[i] = v;
        }

        __syncthreads();
        #pragma unroll
        for (int i = 0; i < 2; i++) {
            As[(af4 + 0) * 66 + arow + 32 * i] = av[i].x;
            As[(af4 + 1) * 66 + arow + 32 * i] = av[i].y;
            As[(af4 + 2) * 66 + arow + 32 * i] = av[i].z;
            As[(af4 + 3) * 66 + arow + 32 * i] = av[i].w;
        }
        *(float4*)(Bs + (size_t)t * 4)         = bv2[0];
        *(float4*)(Bs + (size_t)(t + 256) * 4) = bv2[1];
        __syncthreads();

        #pragma unroll
        for (int k = 0; k < 32; k++) {
            const unsigned long long A0 = *(const unsigned long long*)&As[k * 66 + ty * 4];
            const unsigned long long A1 = *(const unsigned long long*)&As[k * 66 + ty * 4 + 2];
            const float4 bv = *(const float4*)(Bs + k * 64 + tx * 4);
            const unsigned long long Bq0 = dup2(bv.x);
            const unsigned long long Bq1 = dup2(bv.y);
            const unsigned long long Bq2 = dup2(bv.z);
            const unsigned long long Bq3 = dup2(bv.w);
            ffma2(acc[0][0], A0, Bq0); ffma2(acc[1][0], A1, Bq0);
            ffma2(acc[0][1], A0, Bq1); ffma2(acc[1][1], A1, Bq1);
            ffma2(acc[0][2], A0, Bq2); ffma2(acc[1][2], A1, Bq2);
            ffma2(acc[0][3], A0, Bq3); ffma2(acc[1][3], A1, Bq3);
        }
    }

    float* outp = g_part + ((size_t)c * B_ + row0 + ty * 4) * 64 + tx * 4;
    #pragma unroll
    for (int p = 0; p < 2; p++) {
        const float2 u0 = unpk(acc[p][0]);
        const float2 u1 = unpk(acc[p][1]);
        const float2 u2 = unpk(acc[p][2]);
        const float2 u3 = unpk(acc[p][3]);
        *(float4*)(outp + (size_t)(2 * p) * 64)     = make_float4(u0.x, u1.x, u2.x, u3.x);
        *(float4*)(outp + (size_t)(2 * p + 1) * 64) = make_float4(u0.y, u1.y, u2.y, u3.y);
    }
}

// =============================================================================
// Mega kernel — four block populations, ONE launch (exact R11 structure, the
// measured session optimum):
//  [0, 224):    z-GEMM chunks                      -> fence + g_pdone++
//  [224, 474):  gene producers (block completes p-groups {2gb, 2gb+1})
//               -> fence + g_cdone[chunk(s)]++
//  [474, 794):  gene-GEMM consumers: spin g_cdone[c]==13, gemm
//               -> fence + g_pdone++
//  [794, 922):  finish (8 rows/block): pre-stage fW1/fW2, spin g_pdone==544,
//               reduce partials + fusion + MLP -> out. Last block resets ctrs.
// Producers hold low bids -> resident in wave 1; spinners never starve them.
// =============================================================================
__global__ void __launch_bounds__(256, 5) mega_kernel(
    const float* __restrict__ x,
    const float* __restrict__ z1, const float* __restrict__ z2,
    const float* __restrict__ z3,
    const float* __restrict__ Wg, const float* __restrict__ bg,
    const float* __restrict__ W0, const float* __restrict__ b0,
    const float* __restrict__ W1, const float* __restrict__ b1,
    const float* __restrict__ W2, const float* __restrict__ b2,
    const float* __restrict__ W3, const float* __restrict__ b3,
    const float* __restrict__ w1, const float* __restrict__ w2,
    const float* __restrict__ w3,
    const float* __restrict__ fW1, const float* __restrict__ fb1,
    const float* __restrict__ fW2, const float* __restrict__ fb2,
    const float* __restrict__ fW3, const float* __restrict__ fb3,
    float* __restrict__ out)
{
    __shared__ __align__(128) float pool[8720];   // max(GEMM 4160, finish 8720)

    const int bid = blockIdx.x;
    const int t   = threadIdx.x;

    if (bid < NZBLK) {
        const int zc   = bid >> 4;            // 0..13
        const int row0 = (bid & 15) * 64;
        const float* A; const float* W; int lda, k0;
        if (zc < 8)       { A = z1; W = W1; lda = 4096; k0 = zc * 512; }
        else if (zc < 12) { A = z2; W = W2; lda = 2048; k0 = (zc - 8)  * 512; }
        else              { A = z3; W = W3; lda = 1024; k0 = (zc - 12) * 512; }
        gemm_body<true>(pool, pool + 2112, A, W, lda, k0, 512, NGC + zc, row0);
        __syncthreads();
        __threadfence();
        if (t == 0) atomicAdd(&g_pdone, 1);
        return;
    }

    if (bid < NZBLK + GENEBLK) {
        // ---- gene producers: 2000 warp-tasks = 500 p-groups x 4 b-chunks ----
        const int gb   = bid - NZBLK;            // 0..249
        const int lane = t & 31;
        const int w    = gb * 8 + (t >> 5);      // 0..1999
        const int p    = w >> 2;                 // gene group 0..499
        const int b0r  = (w & 3) * 256;          // b-chunk of 256 rows

        const float4 wv  = *(const float4*)(Wg + (size_t)p * 128 + lane * 4);
        const int    g   = p * 4 + (lane >> 3);
        const float  bias = __ldg(bg + g);
        const bool   is_store_lane = (lane & 7) == 0;

        const float* xp = x + (size_t)b0r * ROWSTRIDE + (size_t)p * 128 + lane * 4;
        float* gp = g_gene + (size_t)b0r * G_ + g;

        for (int i = 0; i < 256; i += 8) {
            float4 xv[8];
            #pragma unroll
            for (int j = 0; j < 8; j++)
                xv[j] = __ldcs((const float4*)(xp + (size_t)(i + j) * ROWSTRIDE));

            float d[8];
            #pragma unroll
            for (int j = 0; j < 8; j++)
                d[j] = xv[j].x * wv.x + xv[j].y * wv.y + xv[j].z * wv.z + xv[j].w * wv.w;

            #pragma unroll
            for (int j = 0; j < 8; j++) {
                d[j] += __shfl_down_sync(0xffffffffu, d[j], 4);
                d[j] += __shfl_down_sync(0xffffffffu, d[j], 2);
                d[j] += __shfl_down_sync(0xffffffffu, d[j], 1);
            }
            if (is_store_lane) {
                #pragma unroll
                for (int j = 0; j < 8; j++)
                    gp[(size_t)(i + j) * G_] = fmaxf(d[j] + bias, 0.0f);
            }
        }

        __syncthreads();
        __threadfence();
        if (t == 0) {
            // block gb fully produced p-groups 2gb and 2gb+1
            const int ca  = (2 * gb) / 25;       // 25 p-groups per chunk
            const int cb2 = (2 * gb + 1) / 25;
            atomicAdd(&g_cdone[ca], 1);
            if (cb2 != ca) atomicAdd(&g_cdone[cb2], 1);
        }
        return;
    }

    if (bid < NZBLK + GENEBLK + GGBLK) {
        // ---- gene-GEMM consumers: per-chunk gate ----
        const int cb   = bid - (NZBLK + GENEBLK);   // 0..319
        const int c    = cb >> 4;                   // 0..NGC-1
        const int row0 = (cb & 15) * 64;
        if (t == 0) {
            while (ld_acq(&g_cdone[c]) < CHUNK_TGT) __nanosleep(128);
        }
        __syncthreads();

        gemm_body<false>(pool, pool + 2112, g_gene, W0, G_, c * 100, 100, c, row0);
        __syncthreads();
        __threadfence();
        if (t == 0) atomicAdd(&g_pdone, 1);
        return;
    }

    // ---- finish population: 128 blocks x 8 rows (single-gate form) ----
    float* sW1 = pool;                                   // 4096
    float* sW2 = pool + 4096;                            // 4096
    float (*sbuf)[64] = (float(*)[64])(pool + 8192);     // 8*64
    float* sred = pool + 8192 + 512;                     // 16

    const int h   = t & 63;
    const int r   = t >> 6;       // slot 0..3; thread handles rows r and r+4
    const int wid = t >> 5;

    // PRE-STAGE weights while producers still run
    #pragma unroll
    for (int i = 0; i < 4; i++) {
        ((float4*)sW1)[t + 256 * i] = ((const float4*)fW1)[t + 256 * i];
        ((float4*)sW2)[t + 256 * i] = ((const float4*)fW2)[t + 256 * i];
    }

    if (t == 0) {
        while (ld_acq(&g_pdone) < PDONE_TARGET) __nanosleep(128);
    }
    __syncthreads();   // gate + weight-staging visibility

    const int fb  = bid - (NZBLK + GENEBLK + GGBLK);
    const int b0r = fb * 8;

    float dd[2];
    #pragma unroll
    for (int rr = 0; rr < 2; rr++) {
        const int b = b0r + r + rr * 4;
        float a0 = 0.f, a1 = 0.f, a2 = 0.f, a3 = 0.f;
        #pragma unroll
        for (int cc = 0;       cc < NGC;      cc++) a0 += g_part[((size_t)cc * B_ + b) * 64 + h];
        #pragma unroll
        for (int cc = NGC;     cc < NGC + 8;  cc++) a1 += g_part[((size_t)cc * B_ + b) * 64 + h];
        #pragma unroll
        for (int cc = NGC + 8; cc < NGC + 12; cc++) a2 += g_part[((size_t)cc * B_ + b) * 64 + h];
        #pragma unroll
        for (int cc = NGC + 12; cc < NGC + 14; cc++) a3 += g_part[((size_t)cc * B_ + b) * 64 + h];

        float d = fmaxf(a0 + b0[h], 0.f);
        d += fmaxf(a1 + b1[h], 0.f) * w1[h];
        d += fmaxf(a2 + b2[h], 0.f) * w2[h];
        d += fmaxf(a3 + b3[h], 0.f) * w3[h];
        dd[rr] = d;
    }

    sbuf[r][h]     = dd[0];
    sbuf[r + 4][h] = dd[1];
    __syncthreads();
    float acc0 = fb1[h], acc1 = fb1[h];
    #pragma unroll
    for (int k = 0; k < 64; k++) {
        acc0 = fmaf(sbuf[r][k],     sW1[k * 64 + h], acc0);
        acc1 = fmaf(sbuf[r + 4][k], sW1[k * 64 + h], acc1);
    }
    const float hv0 = fmaxf(acc0, 0.f);
    const float hv1 = fmaxf(acc1, 0.f);
    __syncthreads();
    sbuf[r][h]     = hv0;
    sbuf[r + 4][h] = hv1;
    __syncthreads();
    acc0 = fb2[h]; acc1 = fb2[h];
    #pragma unroll
    for (int k = 0; k < 64; k++) {
        acc0 = fmaf(sbuf[r][k],     sW2[k * 64 + h], acc0);
        acc1 = fmaf(sbuf[r + 4][k], sW2[k * 64 + h], acc1);
    }
    const float h20 = fmaxf(acc0, 0.f);
    const float h21 = fmaxf(acc1, 0.f);

    float v0 = h20 * fW3[h];
    float v1 = h21 * fW3[h];
    #pragma unroll
    for (int off = 16; off; off >>= 1) {
        v0 += __shfl_down_sync(0xffffffffu, v0, off);
        v1 += __shfl_down_sync(0xffffffffu, v1, off);
    }
    if ((t & 31) == 0) { sred[wid] = v0; sred[8 + wid] = v1; }
    __syncthreads();
    if (h == 0) {
        out[b0r + r]     = sred[2 * r] + sred[2 * r + 1] + fb3[0];
        out[b0r + r + 4] = sred[8 + 2 * r] + sred[8 + 2 * r + 1] + fb3[0];
    }

    // Counter reset by the LAST finish block (all gates passed by then).
    __syncthreads();
    if (t == 0) {
        const int o = atomicAdd(&g_fin, 1);
        if (o == FINBLK - 1) {
            #pragma unroll
            for (int c = 0; c < NGC; c++) g_cdone[c] = 0;
            g_pdone = 0;
            g_fin   = 0;
            __threadfence();
        }
    }
}

// =============================================================================
// Launcher (graph-capturable: ONE kernel launch, no sync, no alloc)
// =============================================================================
extern "C" void kernel_launch(void* const* d_in, const int* in_sizes, int n_in,
                              void* d_out, int out_size)
{
    const float* x   = (const float*)d_in[0];
    const float* z1  = (const float*)d_in[1];
    const float* z2  = (const float*)d_in[2];
    const float* z3  = (const float*)d_in[3];
    const float* Wg  = (const float*)d_in[4];
    const float* bg  = (const float*)d_in[5];
    const float* W0  = (const float*)d_in[6];
    const float* b0  = (const float*)d_in[7];
    const float* W1  = (const float*)d_in[8];
    const float* b1  = (const float*)d_in[9];
    const float* W2  = (const float*)d_in[10];
    const float* b2  = (const float*)d_in[11];
    const float* W3  = (const float*)d_in[12];
    const float* b3  = (const float*)d_in[13];
    const float* w1  = (const float*)d_in[14];
    const float* w2  = (const float*)d_in[15];
    const float* w3  = (const float*)d_in[16];
    const float* fW1 = (const float*)d_in[17];
    const float* fb1 = (const float*)d_in[18];
    const float* fW2 = (const float*)d_in[19];
    const float* fb2 = (const float*)d_in[20];
    const float* fW3 = (const float*)d_in[21];
    const float* fb3 = (const float*)d_in[22];
    float* out = (float*)d_out;

    mega_kernel<<<NZBLK + GENEBLK + GGBLK + FINBLK, 256>>>(
        x, z1, z2, z3, Wg, bg, W0, b0, W1, b1, W2, b2, W3, b3,
        w1, w2, w3, fW1, fb1, fW2, fb2, fW3, fb3, out);
}